// round 6
// baseline (speedup 1.0000x reference)
#include <cuda_runtime.h>

// CapsNet dynamic routing, factorized (u never materialized), BT=2 batches/CTA.
// Bank-conflict-free layouts: c plane stride CS=1189 with u-stride 33;
// x swizzle q = i ^ ((i>>3)&7) ^ (((i>>8)&3)<<1); pb u-stride 81 float4.

namespace {
constexpr int O_ = 10, U_ = 36, E_ = 16, F_ = 8;
constexpr int N_ = 1152;
constexpr int B_ = 256;
constexpr int BT = 2;
constexpr int T_ = 1024;             // 32 warps, 1 CTA/SM
constexpr int CS = 1189;             // c plane stride (mod 32 == 5)

// shared layout (floats)
constexpr int OFF_XS = 0;                        // swizzled x [BT][N][F]   18432
constexpr int OFF_C  = OFF_XS + BT * N_ * F_;    // c 20 planes of CS       23784 (padded)
constexpr int OFF_P  = OFF_C + 23784;            // pb 2916 float4          11664
constexpr int OFF_VV = OFF_P + 11664;            // [BT][O][E]                320
constexpr int SM_FLOATS = OFF_VV + BT * O_ * E_; // 54200 -> 216,800 B
} // namespace

__device__ __forceinline__ int xsw(int i) {
    return i ^ ((i >> 3) & 7) ^ (((i >> 8) & 3) << 1);
}

__global__ __launch_bounds__(T_, 1)
void caps_route_kernel(const float* __restrict__ x,
                       const float* __restrict__ Wg,
                       float* __restrict__ out) {
    extern __shared__ float sm[];
    float* xs = sm + OFF_XS;
    float* cc = sm + OFF_C;
    float* vv = sm + OFF_VV;
    float4* pb4 = reinterpret_cast<float4*>(sm + OFF_P);

    const int tid = threadIdx.x;
    const int b0 = blockIdx.x * BT;

    const float4* __restrict__ wp4 = reinterpret_cast<const float4*>(Wg);
    float4* xs4 = reinterpret_cast<float4*>(xs);

    // ---- load x tiles (coalesced gmem read, swizzled smem store); c = 1/O ----
    {
        const float4* xg = reinterpret_cast<const float4*>(x) + (size_t)b0 * (N_ * F_ / 4);
        #pragma unroll
        for (int i = tid; i < BT * N_ * F_ / 4; i += T_) {
            xs4[xsw(i)] = xg[i];
        }
    }
    for (int i = tid; i < 20 * CS; i += T_) cc[i] = 0.1f;
    __syncthreads();

    // P2 task decode (576 tasks): tid = u<<4 | oh<<3 | fg<<2 | bb<<1 | sh
    const int p2_sh = tid & 1;
    const int p2_bb = (tid >> 1) & 1;
    const int p2_fg = (tid >> 2) & 1;
    const int p2_oh = (tid >> 3) & 1;
    const int p2_u  = tid >> 4;
    const float* p2_cb = cc + (p2_bb * 10 + p2_oh * 5) * CS + p2_u * 33 + p2_sh * 16;
    const int p2_pbase = (p2_bb * N_ + p2_u * 32 + p2_sh * 16) * 2 + p2_fg;
    float4* p2_pr = pb4 + p2_u * 81 + (tid & 15) * 5;

    // P3 decode: warp owns (bb,o); lanes = (e low 4 bits, ch bit 4)
    const int warp = tid >> 5;
    const int p3_e  = tid & 15;
    const int p3_ch = (tid >> 4) & 1;
    const int p3_bb = (warp >= 10);
    const int p3_o  = warp - 10 * p3_bb;
    const int p3_oh = (p3_o >= 5);
    const int p3_k  = p3_o - 5 * p3_oh;
    const int p3_rb = (p3_oh * 8 + p3_bb * 2) * 5 + p3_k;   // r*5 + k base (fg=sh=0)

    for (int it = 0; it < 4; ++it) {
        // ---- P2: y partials for (bb,u,fg,oh,sh); 5 o-accumulators ----
        if (tid < 576) {
            float4 a0 = make_float4(0.f,0.f,0.f,0.f), a1 = a0, a2 = a0, a3 = a0, a4 = a0;
            #pragma unroll
            for (int j = 0; j < 16; ++j) {
                const int s = (p2_u + j) & 15;          // rotation: spread banks
                const float4 xv = xs4[xsw(p2_pbase + 2 * s)];
                const float c0 = p2_cb[s];
                const float c1 = p2_cb[CS + s];
                const float c2 = p2_cb[2 * CS + s];
                const float c3 = p2_cb[3 * CS + s];
                const float c4 = p2_cb[4 * CS + s];
                a0.x += c0 * xv.x; a0.y += c0 * xv.y; a0.z += c0 * xv.z; a0.w += c0 * xv.w;
                a1.x += c1 * xv.x; a1.y += c1 * xv.y; a1.z += c1 * xv.z; a1.w += c1 * xv.w;
                a2.x += c2 * xv.x; a2.y += c2 * xv.y; a2.z += c2 * xv.z; a2.w += c2 * xv.w;
                a3.x += c3 * xv.x; a3.y += c3 * xv.y; a3.z += c3 * xv.z; a3.w += c3 * xv.w;
                a4.x += c4 * xv.x; a4.y += c4 * xv.y; a4.z += c4 * xv.z; a4.w += c4 * xv.w;
            }
            p2_pr[0] = a0; p2_pr[1] = a1; p2_pr[2] = a2; p2_pr[3] = a3; p2_pr[4] = a4;
        }
        __syncthreads();

        // ---- P3 (+squash fused): warp (bb,o); lane (e, ch of 18 u) -> vv ----
        if (warp < 20) {
            float p = 0.f;
            #pragma unroll 6
            for (int jj = 0; jj < 18; ++jj) {
                const int u = p3_ch * 18 + jj;
                const int rbase = u * 81 + p3_rb;
                float4 A0 = pb4[rbase];             // fg0 sh0
                const float4 t0 = pb4[rbase + 5];   // fg0 sh1
                float4 A1 = pb4[rbase + 20];        // fg1 sh0
                const float4 t1 = pb4[rbase + 25];  // fg1 sh1
                A0.x += t0.x; A0.y += t0.y; A0.z += t0.z; A0.w += t0.w;
                A1.x += t1.x; A1.y += t1.y; A1.z += t1.z; A1.w += t1.w;
                const int wb = ((p3_o * U_ + u) * E_ + p3_e) * 2;
                const float4 w0 = wp4[wb];
                const float4 w1 = wp4[wb + 1];
                p += w0.x * A0.x + w0.y * A0.y + w0.z * A0.z + w0.w * A0.w
                   + w1.x * A1.x + w1.y * A1.y + w1.z * A1.z + w1.w * A1.w;
            }
            const float s = p + __shfl_xor_sync(0xffffffffu, p, 16);
            float nsq = s * s;
            #pragma unroll
            for (int m = 1; m <= 8; m <<= 1)
                nsq += __shfl_xor_sync(0xffffffffu, nsq, m);
            const float sc = sqrtf(nsq) / (1.f + nsq);
            if (p3_ch == 0)
                vv[(p3_bb * 10 + p3_o) * 16 + p3_e] = s * sc;
        }
        __syncthreads();

        if (it == 3) break;

        // ---- P5: wv[bb,o,u,fg] into pb (aliased); one W read serves both bb ----
        if (tid < 720) {
            const int fg = tid & 1;
            const int ou = tid >> 1;
            const int o = ou / U_, u = ou - o * U_;
            const float4* wp = wp4 + ((o * U_ + u) * E_) * 2 + fg;
            const float* v0 = vv + o * 16;
            const float* v1 = v0 + 160;
            float4 A = make_float4(0.f,0.f,0.f,0.f);
            float4 Bv = A;
            #pragma unroll
            for (int e = 0; e < E_; ++e) {
                const float4 w = wp[e * 2];
                const float ve0 = v0[e], ve1 = v1[e];
                A.x  += ve0 * w.x; A.y  += ve0 * w.y; A.z  += ve0 * w.z; A.w  += ve0 * w.w;
                Bv.x += ve1 * w.x; Bv.y += ve1 * w.y; Bv.z += ve1 * w.z; Bv.w += ve1 * w.w;
            }
            pb4[(o * U_ + u) * 2 + fg] = A;
            pb4[720 + (o * U_ + u) * 2 + fg] = Bv;
        }
        __syncthreads();

        // ---- P6: c <- normalize_o( c * exp(x . wv) ) ----
        #pragma unroll
        for (int kk = 0; kk < 3; ++kk) {
            const int idx = tid + T_ * kk;
            if (idx < BT * N_) {
                const int bb = (idx >= N_);
                const int n = idx - bb * N_;
                const int u = n >> 5;
                const int q = xsw((bb * N_ + n) * 2);
                const float4 x0 = xs4[q];
                const float4 x1 = xs4[q ^ 1];
                const float4* wvb = pb4 + bb * 720 + u * 2;
                float* cp = cc + (bb * 10) * CS + u * 33 + (n & 31);
                float t[O_];
                float ss = 0.f;
                #pragma unroll
                for (int o = 0; o < O_; ++o) {
                    const float4 w0 = wvb[o * 72], w1 = wvb[o * 72 + 1];
                    const float d = x0.x * w0.x + x0.y * w0.y + x0.z * w0.z + x0.w * w0.w
                                  + x1.x * w1.x + x1.y * w1.y + x1.z * w1.z + x1.w * w1.w;
                    const float tv = cp[o * CS] * __expf(d);
                    t[o] = tv;
                    ss += tv;
                }
                const float inv = 1.0f / ss;
                #pragma unroll
                for (int o = 0; o < O_; ++o) cp[o * CS] = t[o] * inv;
            }
        }
        __syncthreads();
    }

    // ---- write out[b][o][e] ----
    if (tid < BT * O_ * E_) {
        const int bb = tid / (O_ * E_);
        out[(size_t)(b0 + bb) * (O_ * E_) + (tid - bb * O_ * E_)] = vv[tid];
    }
}

extern "C" void kernel_launch(void* const* d_in, const int* in_sizes, int n_in,
                              void* d_out, int out_size) {
    (void)in_sizes; (void)n_in; (void)out_size;
    const float* x = (const float*)d_in[0];
    const float* W = (const float*)d_in[1];
    float* out = (float*)d_out;

    const size_t smem = (size_t)SM_FLOATS * sizeof(float);  // 216,800 B
    cudaFuncSetAttribute(caps_route_kernel,
                         cudaFuncAttributeMaxDynamicSharedMemorySize, (int)smem);
    caps_route_kernel<<<B_ / BT, T_, smem>>>(x, W, out);
}